// round 12
// baseline (speedup 1.0000x reference)
#include <cuda_runtime.h>
#include <cuda_bf16.h>
#include <math.h>
#include <stdint.h>

#define BB 8
#define TT 2048
#define II 1024
#define HH 1024
#define G4 4096
#define OO 4096
#define NB 128

typedef unsigned long long ull;

// ---------------- scratch (no allocations allowed) ----------------
__device__ float g_xg[(size_t)BB * TT * G4];   // [b][t][4H] input-gate precompute
__device__ float g_h[2][HH * BB];              // fp32 h (pair layout) — fc only
__device__ uint2 g_hb[2][HH / 2][BB];          // packed bf16 {hi, lo} per (kp, b)
__device__ unsigned int g_tag[2][NB][32];      // per-slot per-producer tags (128B lines)
__device__ volatile unsigned int g_flags[NB * 32];  // barrier arrival flags
__device__ volatile unsigned int g_sense;           // barrier release word

// packed f32x2 helpers
#define FMA2(d, a, b) asm("fma.rn.f32x2 %0, %1, %2, %0;" : "+l"(d) : "l"(a), "l"(b))
#define PACK2(d, s)   asm("mov.b64 %0, {%1, %1};" : "=l"(d) : "f"(s))

__device__ __forceinline__ float tanh_fast(float x) {
    float y; asm("tanh.approx.f32 %0, %1;" : "=f"(y) : "f"(x)); return y;
}
__device__ __forceinline__ float sigmoid_fast(float x) {
    return 0.5f + 0.5f * tanh_fast(0.5f * x);
}
__device__ __forceinline__ unsigned int ld_acq(const unsigned int* p) {
    unsigned int v;
    asm volatile("ld.acquire.gpu.u32 %0, [%1];" : "=r"(v) : "l"(p) : "memory");
    return v;
}
__device__ __forceinline__ void st_rel(unsigned int* p, unsigned int v) {
    asm volatile("st.release.gpu.u32 [%0], %1;" :: "l"(p), "r"(v) : "memory");
}

// ---- bf16 hi/lo split helpers ----
__device__ __forceinline__ uint32_t prmt_hi(float x, float y) {
    uint32_t r;
    asm("prmt.b32 %0, %1, %2, 0x7632;" : "=r"(r)
        : "r"(__float_as_uint(x)), "r"(__float_as_uint(y)));
    return r;
}
__device__ __forceinline__ float trunc_bf(float x) {
    return __uint_as_float(__float_as_uint(x) & 0xFFFF0000u);
}
__device__ __forceinline__ uint32_t bf2(float lo, float hi) {
    uint32_t r;
    asm("cvt.rn.bf16x2.f32 %0, %1, %2;" : "=r"(r) : "f"(hi), "f"(lo));
    return r;
}

// mma.sync m16n8k16 row.col bf16 -> f32 accumulate
#define MMA16816(d, a, b0, b1) \
    asm volatile("mma.sync.aligned.m16n8k16.row.col.f32.bf16.bf16.f32 " \
        "{%0,%1,%2,%3}, {%4,%5,%6,%7}, {%8,%9}, {%0,%1,%2,%3};" \
        : "+f"((d)[0]), "+f"((d)[1]), "+f"((d)[2]), "+f"((d)[3]) \
        : "r"((a)[0]), "r"((a)[1]), "r"((a)[2]), "r"((a)[3]), \
          "r"(b0), "r"(b1))

#define BARX(id, cnt) asm volatile("bar.sync %0, %1;" :: "r"(id), "r"(cnt) : "memory")

// no-op dummies: keep ncu's -s 5 capture on lstm_rec_kernel
__global__ void dummy_kernel() {}

// =================================================================
// Kernel 1: xg = x @ W_ih^T + (b_ih+b_hh)   (exact proven R1 kernel)
// =================================================================
#define BM 128
#define BN 128
#define BK 16
#define LDP 132

__global__ __launch_bounds__(256) void gemm_xg_kernel(
    const float* __restrict__ x, const float* __restrict__ Wih,
    const float* __restrict__ bih, const float* __restrict__ bhh)
{
    __shared__ float As[BK][LDP];
    __shared__ float Ws[BK][LDP];
    const int tid = threadIdx.x;
    const int m0 = blockIdx.y * BM;
    const int n0 = blockIdx.x * BN;
    const int tx = tid & 15;
    const int ty = tid >> 4;

    ull acc[4][8];
#pragma unroll
    for (int p = 0; p < 4; p++)
#pragma unroll
        for (int n = 0; n < 8; n++) acc[p][n] = 0ull;

    for (int k0 = 0; k0 < II; k0 += BK) {
#pragma unroll
        for (int r = 0; r < 2; r++) {
            int f = tid + r * 256;
            int m = f >> 2, kq = f & 3;
            float4 v = *(const float4*)&x[(size_t)(m0 + m) * II + k0 + kq * 4];
            As[kq * 4 + 0][m] = v.x;
            As[kq * 4 + 1][m] = v.y;
            As[kq * 4 + 2][m] = v.z;
            As[kq * 4 + 3][m] = v.w;
        }
#pragma unroll
        for (int r = 0; r < 2; r++) {
            int f = tid + r * 256;
            int n = f >> 2, kq = f & 3;
            float4 v = *(const float4*)&Wih[(size_t)(n0 + n) * II + k0 + kq * 4];
            Ws[kq * 4 + 0][n] = v.x;
            Ws[kq * 4 + 1][n] = v.y;
            Ws[kq * 4 + 2][n] = v.z;
            Ws[kq * 4 + 3][n] = v.w;
        }
        __syncthreads();
#pragma unroll
        for (int kk = 0; kk < BK; kk++) {
            const ulonglong2 a01 = *(const ulonglong2*)&As[kk][ty * 8];
            const ulonglong2 a23 = *(const ulonglong2*)&As[kk][ty * 8 + 4];
            const float4 w0 = *(const float4*)&Ws[kk][tx * 8];
            const float4 w1 = *(const float4*)&Ws[kk][tx * 8 + 4];
            ull wd[8];
            PACK2(wd[0], w0.x); PACK2(wd[1], w0.y);
            PACK2(wd[2], w0.z); PACK2(wd[3], w0.w);
            PACK2(wd[4], w1.x); PACK2(wd[5], w1.y);
            PACK2(wd[6], w1.z); PACK2(wd[7], w1.w);
#pragma unroll
            for (int n = 0; n < 8; n++) {
                FMA2(acc[0][n], a01.x, wd[n]);
                FMA2(acc[1][n], a01.y, wd[n]);
                FMA2(acc[2][n], a23.x, wd[n]);
                FMA2(acc[3][n], a23.y, wd[n]);
            }
        }
        __syncthreads();
    }

    float bias[8];
#pragma unroll
    for (int n = 0; n < 8; n++) {
        int nn = n0 + tx * 8 + n;
        bias[n] = bih[nn] + bhh[nn];
    }
#pragma unroll
    for (int p = 0; p < 4; p++) {
        float r0[8], r1[8];
#pragma unroll
        for (int n = 0; n < 8; n++) {
            float2 f = *(float2*)&acc[p][n];
            r0[n] = f.x + bias[n];
            r1[n] = f.y + bias[n];
        }
        const size_t m = (size_t)(m0 + ty * 8 + 2 * p);
        float* o0 = &g_xg[m * G4 + n0 + tx * 8];
        float* o1 = o0 + G4;
        *(float4*)o0       = make_float4(r0[0], r0[1], r0[2], r0[3]);
        *((float4*)o0 + 1) = make_float4(r0[4], r0[5], r0[6], r0[7]);
        *(float4*)o1       = make_float4(r1[0], r1[1], r1[2], r1[3]);
        *((float4*)o1 + 1) = make_float4(r1[4], r1[5], r1[6], r1[7]);
    }
}

// =================================================================
// Kernel 2: persistent LSTM, warp-specialized. 128 CTAs x 608 thr.
//   warps 0-15 : compute (poll own 8 producers' tags, LDG B-frags,
//                24 HMMA bf16 hi/lo, STS partials)
//   warps 16-17: tail (reduce+gates+cell-in-regs+pack+publish)
//   warp 18    : collector (CTA0 only) — flags -> sense, OFF the
//                critical path; only packers wait on sense (lagged 1
//                step: anti-dependency for slot overwrite).
//   Protocol: per-slot tags, equality polls (miss-free: producers
//   gated <=1 step ahead by sense; replay-stale tags never alias).
// =================================================================
#define CPB 8
#define KCW 64
#define NW 16
#define CWT 512          // compute threads
#define ABT 576          // compute + tail (barrier A/B count)
#define THR 608

__global__ __launch_bounds__(THR, 1) void lstm_rec_kernel(const float* __restrict__ Whh)
{
    __shared__ float part[NW][32][8];   // 16KB [warp][local gate row][batch]

    const int tid = threadIdx.x;
    const int w = tid >> 5;
    const int l = tid & 31;
    const int bid = blockIdx.x;
    const int c0 = bid * CPB;

    // ================= collector warp (CTA0 only) =================
    if (w == 18) {
        if (bid != 0) return;
        for (int t = 0; t < TT; t++) {
            const unsigned int tgt = (unsigned int)(t + 1);
#pragma unroll
            for (int r = 0; r < 4; r++) {
                const int p = l + r * 32;
                while (g_flags[p * 32] != tgt) __nanosleep(32);
            }
            __syncwarp();
            if (l == 0) {
                __threadfence();
                g_sense = tgt;
            }
        }
        return;
    }

    // ================= tail warps (w == 16, 17) =================
    if (w >= NW) {
        const int tl = tid - CWT;        // 0..63
        const int cc = tl >> 3;          // h column within CTA
        const int b = tl & 7;            // batch
        const float* xg_base = &g_xg[((size_t)b * TT) * G4 + c0 + cc];
        float c_reg = 0.f;
        const int hcol = c0 + cc;

        for (int t = 0; t < TT; t++) {
            const int ws = (t & 1) ^ 1;
            // prefetch xg early (overlaps barriers)
            const float* p = xg_base + (size_t)t * G4;
            const float xg0 = __ldcs(p);
            const float xg1 = __ldcs(p + HH);
            const float xg2 = __ldcs(p + 2 * HH);
            const float xg3 = __ldcs(p + 3 * HH);

            BARX(2, ABT);    // A: previous tail reads done (for compute STS)
            BARX(3, ABT);    // B: this step's partials ready

            float g0 = xg0, g1 = xg1, g2 = xg2, g3 = xg3;
#pragma unroll
            for (int ww = 0; ww < NW; ww++) {
                g0 += part[ww][0 * 8 + cc][b];
                g1 += part[ww][1 * 8 + cc][b];
                g2 += part[ww][2 * 8 + cc][b];
                g3 += part[ww][3 * 8 + cc][b];
            }
            const float ig = sigmoid_fast(g0);
            const float fg = sigmoid_fast(g1);
            const float gg = tanh_fast(g2);
            const float og = sigmoid_fast(g3);
            c_reg = fg * c_reg + ig * gg;
            const float h = og * tanh_fast(c_reg);
            g_h[ws][(hcol >> 1) * 16 + b * 2 + (hcol & 1)] = h;   // fc only

            // anti-dependency: all CTAs must have finished step t-1 reads
            if (t > 0) {
                while (g_sense != (unsigned int)t) __nanosleep(32);
            }
            // pack bf16 hi/lo: partner h from lane+8 (same warp)
            const float ho = __shfl_down_sync(0xffffffffu, h, 8);
            if ((cc & 1) == 0) {
                uint2 pk;
                pk.x = prmt_hi(h, ho);
                pk.y = bf2(h - trunc_bf(h), ho - trunc_bf(ho));
                g_hb[ws][bid * 4 + (cc >> 1)][b] = pk;
            }
            BARX(4, 64);     // all tail stores done
            if (tl == 0) {
                __threadfence();
                st_rel(&g_tag[ws][bid][0], (unsigned int)(t + 1));
                g_flags[bid * 32] = (unsigned int)(t + 1);
            }
        }
        return;
    }

    // ================= compute warps (w < 16) =================
    const int kb = w * KCW;
    const int kph = w * 32;
    const int g = l >> 2;
    const int t4 = l & 3;

    // W fragments in registers (built once): [mtile][ktile][4] hi+lo
    uint32_t whi[2][4][4], wlo[2][4][4];
#pragma unroll
    for (int m = 0; m < 2; m++) {
        const int r0 = m * 16 + g, r1 = r0 + 8;
        const size_t wr0 = ((size_t)((r0 >> 3) * HH + c0 + (r0 & 7))) * HH;
        const size_t wr1 = ((size_t)((r1 >> 3) * HH + c0 + (r1 & 7))) * HH;
#pragma unroll
        for (int j = 0; j < 4; j++) {
            const int k0 = kb + j * 16 + 2 * t4;
            float2 p0 = *(const float2*)&Whh[wr0 + k0];
            float2 p1 = *(const float2*)&Whh[wr1 + k0];
            float2 p2 = *(const float2*)&Whh[wr0 + k0 + 8];
            float2 p3 = *(const float2*)&Whh[wr1 + k0 + 8];
            whi[m][j][0] = prmt_hi(p0.x, p0.y);
            whi[m][j][1] = prmt_hi(p1.x, p1.y);
            whi[m][j][2] = prmt_hi(p2.x, p2.y);
            whi[m][j][3] = prmt_hi(p3.x, p3.y);
            wlo[m][j][0] = bf2(p0.x - trunc_bf(p0.x), p0.y - trunc_bf(p0.y));
            wlo[m][j][1] = bf2(p1.x - trunc_bf(p1.x), p1.y - trunc_bf(p1.y));
            wlo[m][j][2] = bf2(p2.x - trunc_bf(p2.x), p2.y - trunc_bf(p2.y));
            wlo[m][j][3] = bf2(p3.x - trunc_bf(p3.x), p3.y - trunc_bf(p3.y));
        }
    }

    for (int t = 0; t < TT; t++) {
        const int rs = t & 1;

        float d0h[4] = {0.f, 0.f, 0.f, 0.f}, d0c[4] = {0.f, 0.f, 0.f, 0.f};
        float d1h[4] = {0.f, 0.f, 0.f, 0.f}, d1c[4] = {0.f, 0.f, 0.f, 0.f};
        if (t > 0) {
            // poll MY 8 producers' tags (lane i < 8 -> producer w*8+i)
            if (l < 8) {
                const unsigned int* tp = &g_tag[rs][w * 8 + l][0];
                while (ld_acq(tp) != (unsigned int)t) __nanosleep(20);
            }
            __syncwarp();
#pragma unroll
            for (int j = 0; j < 4; j++) {
                const int kpA = kph + j * 8 + t4;
                const uint2 va = __ldcg(&g_hb[rs][kpA][g]);      // {hi, lo}
                const uint2 vb = __ldcg(&g_hb[rs][kpA + 4][g]);
                MMA16816(d0h, whi[0][j], va.x, vb.x);
                MMA16816(d1h, whi[1][j], va.x, vb.x);
                MMA16816(d0c, whi[0][j], va.y, vb.y);
                MMA16816(d1c, whi[1][j], va.y, vb.y);
                MMA16816(d0c, wlo[0][j], va.x, vb.x);
                MMA16816(d1c, wlo[1][j], va.x, vb.x);
            }
        }

        BARX(2, ABT);    // A: tail finished reading previous partials
        *(float2*)&part[w][g][t4 * 2]      = make_float2(d0h[0] + d0c[0], d0h[1] + d0c[1]);
        *(float2*)&part[w][g + 8][t4 * 2]  = make_float2(d0h[2] + d0c[2], d0h[3] + d0c[3]);
        *(float2*)&part[w][g + 16][t4 * 2] = make_float2(d1h[0] + d1c[0], d1h[1] + d1c[1]);
        *(float2*)&part[w][g + 24][t4 * 2] = make_float2(d1h[2] + d1c[2], d1h[3] + d1c[3]);
        BARX(3, ABT);    // B: partials ready for tail
    }
}

// =================================================================
// Kernel 3: out = hT @ W_fc^T + b_fc  (g_h[0], pair layout)
// =================================================================
__global__ __launch_bounds__(256) void fc_kernel(
    const float* __restrict__ Wfc, const float* __restrict__ bfc,
    float* __restrict__ out)
{
    const int o = blockIdx.x;
    const int tid = threadIdx.x;
    float acc[BB];
#pragma unroll
    for (int b = 0; b < BB; b++) acc[b] = 0.f;

    for (int k = tid; k < HH; k += 256) {
        const float wv = Wfc[(size_t)o * HH + k];
        const int base = (k >> 1) * 16 + (k & 1);
#pragma unroll
        for (int b = 0; b < BB; b++) acc[b] += wv * g_h[0][base + b * 2];
    }
    const int lane = tid & 31, wrp = tid >> 5;
#pragma unroll
    for (int off = 16; off; off >>= 1)
#pragma unroll
        for (int b = 0; b < BB; b++)
            acc[b] += __shfl_down_sync(0xffffffffu, acc[b], off);

    __shared__ float red[8][BB];
    if (lane == 0)
#pragma unroll
        for (int b = 0; b < BB; b++) red[wrp][b] = acc[b];
    __syncthreads();
    if (tid < BB) {
        float s = bfc[o];
#pragma unroll
        for (int ww = 0; ww < 8; ww++) s += red[ww][tid];
        out[(size_t)tid * OO + o] = s;
    }
}

// =================================================================
extern "C" void kernel_launch(void* const* d_in, const int* in_sizes, int n_in,
                              void* d_out, int out_size)
{
    const float* x    = (const float*)d_in[0];
    const float* Wih  = (const float*)d_in[1];
    const float* Whh  = (const float*)d_in[2];
    const float* bih  = (const float*)d_in[3];
    const float* bhh  = (const float*)d_in[4];
    const float* Wfc  = (const float*)d_in[5];
    const float* bfc  = (const float*)d_in[6];
    float* out = (float*)d_out;

    dummy_kernel<<<1, 32>>>();
    dummy_kernel<<<1, 32>>>();
    dim3 g1(G4 / BN, (BB * TT) / BM);
    gemm_xg_kernel<<<g1, 256>>>(x, Wih, bih, bhh);
    lstm_rec_kernel<<<NB, THR>>>(Whh);
    fc_kernel<<<OO, 256>>>(Wfc, bfc, out);
    (void)in_sizes; (void)n_in; (void)out_size;
}

// round 13
// speedup vs baseline: 1.2794x; 1.2794x over previous
#include <cuda_runtime.h>
#include <cuda_bf16.h>
#include <math.h>
#include <stdint.h>

#define BB 8
#define TT 2048
#define II 1024
#define HH 1024
#define G4 4096
#define OO 4096
#define NB 128

typedef unsigned long long ull;

// ---------------- scratch (no allocations allowed) ----------------
__device__ float g_xg[(size_t)BB * TT * G4];   // [b][t][4H] input-gate precompute
__device__ float g_h[HH * BB];                 // fp32 hT (pair layout) — fc only
__device__ uint2 g_hb[2][HH / 2][BB];          // packed bf16 {hi, lo} per (kp, b)
__device__ volatile unsigned int g_flags[NB * 32];  // one 128B line per CTA
__device__ volatile unsigned int g_sense;

// packed f32x2 helpers
#define FMA2(d, a, b) asm("fma.rn.f32x2 %0, %1, %2, %0;" : "+l"(d) : "l"(a), "l"(b))
#define PACK2(d, s)   asm("mov.b64 %0, {%1, %1};" : "=l"(d) : "f"(s))

__device__ __forceinline__ float tanh_fast(float x) {
    float y; asm("tanh.approx.f32 %0, %1;" : "=f"(y) : "f"(x)); return y;
}
__device__ __forceinline__ float sigmoid_fast(float x) {
    return 0.5f + 0.5f * tanh_fast(0.5f * x);
}

// ---- bf16 hi/lo split helpers ----
__device__ __forceinline__ uint32_t prmt_hi(float x, float y) {
    uint32_t r;
    asm("prmt.b32 %0, %1, %2, 0x7632;" : "=r"(r)
        : "r"(__float_as_uint(x)), "r"(__float_as_uint(y)));
    return r;
}
__device__ __forceinline__ float trunc_bf(float x) {
    return __uint_as_float(__float_as_uint(x) & 0xFFFF0000u);
}
__device__ __forceinline__ uint32_t bf2(float lo, float hi) {
    uint32_t r;
    asm("cvt.rn.bf16x2.f32 %0, %1, %2;" : "=r"(r) : "f"(hi), "f"(lo));
    return r;
}

// mma.sync m16n8k16 row.col bf16 -> f32 accumulate
#define MMA16816(d, a, b0, b1) \
    asm volatile("mma.sync.aligned.m16n8k16.row.col.f32.bf16.bf16.f32 " \
        "{%0,%1,%2,%3}, {%4,%5,%6,%7}, {%8,%9}, {%0,%1,%2,%3};" \
        : "+f"((d)[0]), "+f"((d)[1]), "+f"((d)[2]), "+f"((d)[3]) \
        : "r"((a)[0]), "r"((a)[1]), "r"((a)[2]), "r"((a)[3]), \
          "r"(b0), "r"(b1))

// no-op dummies: keep ncu's -s 5 capture on lstm_rec_kernel
__global__ void dummy_kernel() {}

// =================================================================
// Kernel 1: xg = x @ W_ih^T + (b_ih+b_hh)   (exact proven R1 kernel)
// =================================================================
#define BM 128
#define BN 128
#define BK 16
#define LDP 132

__global__ __launch_bounds__(256) void gemm_xg_kernel(
    const float* __restrict__ x, const float* __restrict__ Wih,
    const float* __restrict__ bih, const float* __restrict__ bhh)
{
    __shared__ float As[BK][LDP];
    __shared__ float Ws[BK][LDP];
    const int tid = threadIdx.x;
    const int m0 = blockIdx.y * BM;
    const int n0 = blockIdx.x * BN;
    const int tx = tid & 15;
    const int ty = tid >> 4;

    ull acc[4][8];
#pragma unroll
    for (int p = 0; p < 4; p++)
#pragma unroll
        for (int n = 0; n < 8; n++) acc[p][n] = 0ull;

    for (int k0 = 0; k0 < II; k0 += BK) {
#pragma unroll
        for (int r = 0; r < 2; r++) {
            int f = tid + r * 256;
            int m = f >> 2, kq = f & 3;
            float4 v = *(const float4*)&x[(size_t)(m0 + m) * II + k0 + kq * 4];
            As[kq * 4 + 0][m] = v.x;
            As[kq * 4 + 1][m] = v.y;
            As[kq * 4 + 2][m] = v.z;
            As[kq * 4 + 3][m] = v.w;
        }
#pragma unroll
        for (int r = 0; r < 2; r++) {
            int f = tid + r * 256;
            int n = f >> 2, kq = f & 3;
            float4 v = *(const float4*)&Wih[(size_t)(n0 + n) * II + k0 + kq * 4];
            Ws[kq * 4 + 0][n] = v.x;
            Ws[kq * 4 + 1][n] = v.y;
            Ws[kq * 4 + 2][n] = v.z;
            Ws[kq * 4 + 3][n] = v.w;
        }
        __syncthreads();
#pragma unroll
        for (int kk = 0; kk < BK; kk++) {
            const ulonglong2 a01 = *(const ulonglong2*)&As[kk][ty * 8];
            const ulonglong2 a23 = *(const ulonglong2*)&As[kk][ty * 8 + 4];
            const float4 w0 = *(const float4*)&Ws[kk][tx * 8];
            const float4 w1 = *(const float4*)&Ws[kk][tx * 8 + 4];
            ull wd[8];
            PACK2(wd[0], w0.x); PACK2(wd[1], w0.y);
            PACK2(wd[2], w0.z); PACK2(wd[3], w0.w);
            PACK2(wd[4], w1.x); PACK2(wd[5], w1.y);
            PACK2(wd[6], w1.z); PACK2(wd[7], w1.w);
#pragma unroll
            for (int n = 0; n < 8; n++) {
                FMA2(acc[0][n], a01.x, wd[n]);
                FMA2(acc[1][n], a01.y, wd[n]);
                FMA2(acc[2][n], a23.x, wd[n]);
                FMA2(acc[3][n], a23.y, wd[n]);
            }
        }
        __syncthreads();
    }

    float bias[8];
#pragma unroll
    for (int n = 0; n < 8; n++) {
        int nn = n0 + tx * 8 + n;
        bias[n] = bih[nn] + bhh[nn];
    }
#pragma unroll
    for (int p = 0; p < 4; p++) {
        float r0[8], r1[8];
#pragma unroll
        for (int n = 0; n < 8; n++) {
            float2 f = *(float2*)&acc[p][n];
            r0[n] = f.x + bias[n];
            r1[n] = f.y + bias[n];
        }
        const size_t m = (size_t)(m0 + ty * 8 + 2 * p);
        float* o0 = &g_xg[m * G4 + n0 + tx * 8];
        float* o1 = o0 + G4;
        *(float4*)o0       = make_float4(r0[0], r0[1], r0[2], r0[3]);
        *((float4*)o0 + 1) = make_float4(r0[4], r0[5], r0[6], r0[7]);
        *(float4*)o1       = make_float4(r1[0], r1[1], r1[2], r1[3]);
        *((float4*)o1 + 1) = make_float4(r1[4], r1[5], r1[6], r1[7]);
    }
}

// =================================================================
// Kernel 2: persistent recurrent LSTM = R9 proven skeleton (10.3ms
//   best) + local chain cuts:
//   - B-fragment LDGs hoisted ahead of all MMAs (MLP=8, one L2 trip)
//   - xg prefetched one full step ahead (DRAM latency off the chain)
//   - tail: cell state in regs, shfl-based pack, g_h store only at
//     final step, sense-wait nanosleep 20
//   128 CTAs x 512 thr, 1 CTA/SM.
// =================================================================
#define CPB 8
#define KCW 64
#define NW 16

__global__ __launch_bounds__(512, 1) void lstm_rec_kernel(const float* __restrict__ Whh)
{
    __shared__ float part[NW][32][8];   // 16KB [warp][local gate row][batch]

    const int tid = threadIdx.x;
    const int w = tid >> 5;
    const int l = tid & 31;
    const int bid = blockIdx.x;
    const int c0 = bid * CPB;
    const int kb = w * KCW;
    const int kph = w * 32;

    const int g = l >> 2;
    const int t4 = l & 3;

    // ---- W fragments in registers (built once): [mtile][ktile][4] hi+lo ----
    uint32_t whi[2][4][4], wlo[2][4][4];
#pragma unroll
    for (int m = 0; m < 2; m++) {
        const int r0 = m * 16 + g, r1 = r0 + 8;
        const size_t wr0 = ((size_t)((r0 >> 3) * HH + c0 + (r0 & 7))) * HH;
        const size_t wr1 = ((size_t)((r1 >> 3) * HH + c0 + (r1 & 7))) * HH;
#pragma unroll
        for (int j = 0; j < 4; j++) {
            const int k0 = kb + j * 16 + 2 * t4;
            float2 p0 = *(const float2*)&Whh[wr0 + k0];
            float2 p1 = *(const float2*)&Whh[wr1 + k0];
            float2 p2 = *(const float2*)&Whh[wr0 + k0 + 8];
            float2 p3 = *(const float2*)&Whh[wr1 + k0 + 8];
            whi[m][j][0] = prmt_hi(p0.x, p0.y);
            whi[m][j][1] = prmt_hi(p1.x, p1.y);
            whi[m][j][2] = prmt_hi(p2.x, p2.y);
            whi[m][j][3] = prmt_hi(p3.x, p3.y);
            wlo[m][j][0] = bf2(p0.x - trunc_bf(p0.x), p0.y - trunc_bf(p0.y));
            wlo[m][j][1] = bf2(p1.x - trunc_bf(p1.x), p1.y - trunc_bf(p1.y));
            wlo[m][j][2] = bf2(p2.x - trunc_bf(p2.x), p2.y - trunc_bf(p2.y));
            wlo[m][j][3] = bf2(p3.x - trunc_bf(p3.x), p3.y - trunc_bf(p3.y));
        }
    }

    const int rcc = tid >> 3, rb8 = tid & 7;   // tail identity (tid < 64)
    const float* xg_base = &g_xg[((size_t)rb8 * TT) * G4 + c0 + rcc];

    float c_reg = 0.f;                          // cell state (tail regs)
    // xg pipeline registers: values for the CURRENT step
    float xg0 = 0.f, xg1 = 0.f, xg2 = 0.f, xg3 = 0.f;
    if (tid < CPB * BB) {
        xg0 = __ldcs(xg_base);
        xg1 = __ldcs(xg_base + HH);
        xg2 = __ldcs(xg_base + 2 * HH);
        xg3 = __ldcs(xg_base + 3 * HH);
    }

    for (int t = 0; t < TT; t++) {
        const int rs = t & 1;
        const int wslot = rs ^ 1;

        // ---- prefetch NEXT step's xg (full step of latency distance) ----
        float nx0 = 0.f, nx1 = 0.f, nx2 = 0.f, nx3 = 0.f;
        if (tid < CPB * BB && t + 1 < TT) {
            const float* p = xg_base + (size_t)(t + 1) * G4;
            nx0 = __ldcs(p);
            nx1 = __ldcs(p + HH);
            nx2 = __ldcs(p + 2 * HH);
            nx3 = __ldcs(p + 3 * HH);
        }

        // ---- HMMA dot: hoisted B-frag loads (MLP=8), then 24 MMAs ----
        float d0h[4] = {0.f, 0.f, 0.f, 0.f}, d0c[4] = {0.f, 0.f, 0.f, 0.f};
        float d1h[4] = {0.f, 0.f, 0.f, 0.f}, d1c[4] = {0.f, 0.f, 0.f, 0.f};
        if (t > 0) {
            uint2 va[4], vb[4];
#pragma unroll
            for (int j = 0; j < 4; j++) {
                const int kpA = kph + j * 8 + t4;
                va[j] = __ldcg(&g_hb[rs][kpA][g]);
                vb[j] = __ldcg(&g_hb[rs][kpA + 4][g]);
            }
#pragma unroll
            for (int j = 0; j < 4; j++) {
                MMA16816(d0h, whi[0][j], va[j].x, vb[j].x);
                MMA16816(d1h, whi[1][j], va[j].x, vb[j].x);
                MMA16816(d0c, whi[0][j], va[j].y, vb[j].y);
                MMA16816(d1c, whi[1][j], va[j].y, vb[j].y);
                MMA16816(d0c, wlo[0][j], va[j].x, vb[j].x);
                MMA16816(d1c, wlo[1][j], va[j].x, vb[j].x);
            }
        }

        *(float2*)&part[w][g][t4 * 2]      = make_float2(d0h[0] + d0c[0], d0h[1] + d0c[1]);
        *(float2*)&part[w][g + 8][t4 * 2]  = make_float2(d0h[2] + d0c[2], d0h[3] + d0c[3]);
        *(float2*)&part[w][g + 16][t4 * 2] = make_float2(d1h[0] + d1c[0], d1h[1] + d1c[1]);
        *(float2*)&part[w][g + 24][t4 * 2] = make_float2(d1h[2] + d1c[2], d1h[3] + d1c[3]);
        __syncthreads();

        // ---- tail: reduce + gates + cell update + pack + early flag ----
        if (tid < CPB * BB) {
            float g0 = xg0, g1 = xg1, g2 = xg2, g3 = xg3;
#pragma unroll
            for (int ww = 0; ww < NW; ww++) {
                g0 += part[ww][0 * 8 + rcc][rb8];
                g1 += part[ww][1 * 8 + rcc][rb8];
                g2 += part[ww][2 * 8 + rcc][rb8];
                g3 += part[ww][3 * 8 + rcc][rb8];
            }
            const float ig = sigmoid_fast(g0);
            const float fg = sigmoid_fast(g1);
            const float gg = tanh_fast(g2);
            const float og = sigmoid_fast(g3);
            c_reg = fg * c_reg + ig * gg;
            const float h = og * tanh_fast(c_reg);

            // pack bf16 hi/lo with partner (cc, cc+1) via shfl (same warp)
            const float ho = __shfl_down_sync(0xffffffffu, h, 8);
            if ((rcc & 1) == 0) {
                uint2 pk;
                pk.x = prmt_hi(h, ho);
                pk.y = bf2(h - trunc_bf(h), ho - trunc_bf(ho));
                g_hb[wslot][bid * 4 + (rcc >> 1)][rb8] = pk;
            }
            if (t == TT - 1) {   // fc-only fp32 copy, final step only
                const int hcol = c0 + rcc;
                g_h[(hcol >> 1) * 16 + rb8 * 2 + (hcol & 1)] = h;
            }
            asm volatile("bar.sync 1, 64;" ::: "memory");
            if (tid == 0) {
                __threadfence();
                g_flags[bid * 32] = (unsigned int)(t + 1);
            }
            // rotate xg pipeline
            xg0 = nx0; xg1 = nx1; xg2 = nx2; xg3 = nx3;
        }

        // ---- grid barrier: collector + nanosleep (proven) ----
        const unsigned int tgt = (unsigned int)(t + 1);
        if (bid == 0) {
            if (tid < NB) {
                while (g_flags[tid * 32] != tgt) __nanosleep(32);
            }
            __syncthreads();
            if (tid == 0) {
                __threadfence();
                g_sense = tgt;
            }
        } else {
            if (tid == 0) {
                while (g_sense != tgt) __nanosleep(20);
                __threadfence();
            }
            __syncthreads();
        }
    }
}

// =================================================================
// Kernel 3: out = hT @ W_fc^T + b_fc  (g_h, pair layout)
// =================================================================
__global__ __launch_bounds__(256) void fc_kernel(
    const float* __restrict__ Wfc, const float* __restrict__ bfc,
    float* __restrict__ out)
{
    const int o = blockIdx.x;
    const int tid = threadIdx.x;
    float acc[BB];
#pragma unroll
    for (int b = 0; b < BB; b++) acc[b] = 0.f;

    for (int k = tid; k < HH; k += 256) {
        const float wv = Wfc[(size_t)o * HH + k];
        const int base = (k >> 1) * 16 + (k & 1);
#pragma unroll
        for (int b = 0; b < BB; b++) acc[b] += wv * g_h[base + b * 2];
    }
    const int lane = tid & 31, wrp = tid >> 5;
#pragma unroll
    for (int off = 16; off; off >>= 1)
#pragma unroll
        for (int b = 0; b < BB; b++)
            acc[b] += __shfl_down_sync(0xffffffffu, acc[b], off);

    __shared__ float red[8][BB];
    if (lane == 0)
#pragma unroll
        for (int b = 0; b < BB; b++) red[wrp][b] = acc[b];
    __syncthreads();
    if (tid < BB) {
        float s = bfc[o];
#pragma unroll
        for (int ww = 0; ww < 8; ww++) s += red[ww][tid];
        out[(size_t)tid * OO + o] = s;
    }
}

// =================================================================
extern "C" void kernel_launch(void* const* d_in, const int* in_sizes, int n_in,
                              void* d_out, int out_size)
{
    const float* x    = (const float*)d_in[0];
    const float* Wih  = (const float*)d_in[1];
    const float* Whh  = (const float*)d_in[2];
    const float* bih  = (const float*)d_in[3];
    const float* bhh  = (const float*)d_in[4];
    const float* Wfc  = (const float*)d_in[5];
    const float* bfc  = (const float*)d_in[6];
    float* out = (float*)d_out;

    dummy_kernel<<<1, 32>>>();
    dummy_kernel<<<1, 32>>>();
    dim3 g1(G4 / BN, (BB * TT) / BM);
    gemm_xg_kernel<<<g1, 256>>>(x, Wih, bih, bhh);
    lstm_rec_kernel<<<NB, 512>>>(Whh);
    fc_kernel<<<OO, 256>>>(Wfc, bfc, out);
    (void)in_sizes; (void)n_in; (void)out_size;
}